// round 13
// baseline (speedup 1.0000x reference)
#include <cuda_runtime.h>
#include <math.h>

#define BB 16
#define SS 12
#define NN 2048
#define HH 64
#define HEADS 4
#define DHD 16
#define EE 32768
#define EPAD_MAX 40960
#define STEPS 12
#define DT6F ((float)(0.1/6.0))

// ---------------- scratch ----------------------------------------------------
__device__ float g_y[BB*NN*HH];
__device__ float g_h[BB*HEADS*NN*DHD];     // [b][hd][n][16]
__device__ float g_es[BB*HEADS*NN];
__device__ float g_ed[BB*HEADS*NN];
__device__ float g_k[BB*NN*HH];
__device__ float g_acc[BB*NN*HH];
__device__ int   g_rowoff[NN+1];           // PADDED (multiples of 4) offsets
__device__ int   g_cnt[NN];
__device__ int   g_cursor[NN];
__device__ int   g_order[NN];
__device__ unsigned int g_csrboth[EPAD_MAX]; // (dst<<16)|src ; 0xFFFFFFFF = pad

// ---------------- f32x2 helpers ----------------------------------------------
__device__ __forceinline__ void fma2(unsigned long long &d, unsigned long long a,
                                     unsigned long long b) {
    asm("fma.rn.f32x2 %0, %1, %2, %0;" : "+l"(d) : "l"(a), "l"(b));
}
__device__ __forceinline__ unsigned long long pack2(float lo, float hi) {
    unsigned long long r;
    asm("mov.b64 %0, {%1,%2};" : "=l"(r) : "f"(lo), "f"(hi));
    return r;
}
__device__ __forceinline__ void unpack2(float &lo, float &hi, unsigned long long v) {
    asm("mov.b64 {%0,%1}, %2;" : "=f"(lo), "=f"(hi) : "l"(v));
}

// ---------------- input projection + counter/sentinel init -------------------
__global__ void k_input(const float* __restrict__ inp, const float* __restrict__ w_in,
                        const float* __restrict__ b_in) {
    int idx = blockIdx.x*blockDim.x + threadIdx.x;
    if (idx < NN) g_cnt[idx] = 0;
    if (idx < EPAD_MAX) g_csrboth[idx] = 0xFFFFFFFFu;
    if (idx >= BB*NN*HH) return;
    int h  = idx & 63;
    int bn = idx >> 6;
    int b  = bn >> 11;
    int n  = bn & 2047;
    const float* ip = inp + ((size_t)(b*SS + 0)*NN + n)*2;
    g_y[idx] = ip[0]*w_in[h] + ip[1]*w_in[64+h] + b_in[h];
}

__global__ void k_hist(const int* __restrict__ dst) {
    int e = blockIdx.x*blockDim.x + threadIdx.x;
    if (e < EE) atomicAdd(&g_cnt[dst[e]], 1);
}

// scan (padded degrees) + degree-sort (single block, 256 threads)
__global__ void k_scan() {
    __shared__ int part[256];
    __shared__ int dh[2][64];
    int t = threadIdx.x;
    if (t < 128) { dh[0][t & 63] = 0; dh[1][t & 63] = 0; }
    int base = t*8;
    int loc[8];
    int s = 0;
    #pragma unroll
    for (int i = 0; i < 8; ++i) {
        loc[i] = s;
        s += (g_cnt[base+i] + 3) & ~3;       // pad each segment to mult of 4
    }
    part[t] = s;
    __syncthreads();
    for (int off = 1; off < 256; off <<= 1) {
        int v = (t >= off) ? part[t-off] : 0;
        __syncthreads();
        part[t] += v;
        __syncthreads();
    }
    int excl = (t == 0) ? 0 : part[t-1];
    #pragma unroll
    for (int i = 0; i < 8; ++i) {
        int v = excl + loc[i];
        g_rowoff[base+i] = v;
        g_cursor[base+i] = v;
    }
    if (t == 255) g_rowoff[NN] = part[255];
    #pragma unroll
    for (int i = 0; i < 8; ++i) {
        int n = base + i;
        int d = min(g_cnt[n], 63);
        atomicAdd(&dh[n >> 10][d], 1);
    }
    __syncthreads();
    if (t < 2) {
        int acc = 0;
        for (int d = 0; d < 64; ++d) { int c = dh[t][d]; dh[t][d] = acc; acc += c; }
    }
    __syncthreads();
    #pragma unroll
    for (int i = 0; i < 8; ++i) {
        int n = base + i;
        int half = n >> 10;
        int d = min(g_cnt[n], 63);
        int pos = atomicAdd(&dh[half][d], 1);
        g_order[half*1024 + pos] = n & 1023;
    }
}

__global__ void k_fill(const int* __restrict__ src, const int* __restrict__ dst) {
    int e = blockIdx.x*blockDim.x + threadIdx.x;
    if (e < EE) {
        int d = dst[e];
        int p = atomicAdd(&g_cursor[d], 1);
        g_csrboth[p] = ((unsigned int)d << 16) | (unsigned int)src[e];
    }
}

// ---------------- stage GEMM v9: v8 layouts at 256 threads/block -------------
// 512 blocks x 256 thr; 64 rows/block; thread tile 2 row-pairs x 4 cols.
// smem 49.9KB -> 4 blocks/SM = 32 warps/SM (8/SMSP) for latency hiding.
#define SD_ULL   (32*65)
#define WHD_ULL  (64*2*16*2)
#define SMEM_GEMM ((SD_ULL + WHD_ULL)*8 + 128*4)

__global__ void __launch_bounds__(256, 4) k_gemm(const float* __restrict__ Wh,
                                                 const float* __restrict__ a_src,
                                                 const float* __restrict__ a_dst,
                                                 float coef) {
    extern __shared__ unsigned long long smg[];
    unsigned long long* sd  = smg;                 // 32 pairs x 65
    unsigned long long* Whd = smg + SD_ULL;        // 4096 (k-interleaved dup)
    float* As = (float*)(smg + SD_ULL + WHD_ULL);
    float* Ad = As + 64;

    int t = threadIdx.x;
    int rowbase = blockIdx.x*64;

    // stage Wh duplicated: Whd[((i*2+q2)*16 + c4)*2 + su], c = c4*4 + q2*2 + su
    #pragma unroll
    for (int it = 0; it < 4; ++it) {
        int idx = it*256 + t;                 // float4 index 0..1023
        int i  = idx >> 4;
        int c0 = (idx & 15)*4;
        float4 w = ((const float4*)Wh)[idx];
        float v[4] = {w.x, w.y, w.z, w.w};
        #pragma unroll
        for (int q = 0; q < 4; ++q) {
            int c = c0 + q;
            int c4i = c >> 2, sub = c & 3;
            Whd[((i*2 + (sub >> 1))*16 + c4i)*2 + (sub & 1)] = pack2(v[q], v[q]);
        }
    }
    if (t < 64) { As[t] = a_src[t]; Ad[t] = a_dst[t]; }

    // stage 64 rows as 32 pairs (y[2p][i], y[2p+1][i]), pad 65
    #pragma unroll
    for (int it = 0; it < 2; ++it) {
        int q  = it*256 + t;                  // 0..511
        int p  = q >> 4;
        int i0 = (q & 15)*4;
        int gr = rowbase + p*2;
        float4 va = *(const float4*)(g_y + (size_t)gr*64 + i0);
        float4 vb = *(const float4*)(g_y + (size_t)(gr+1)*64 + i0);
        if (coef != 0.f) {
            float4 ka = *(const float4*)(g_k + (size_t)gr*64 + i0);
            float4 kb = *(const float4*)(g_k + (size_t)(gr+1)*64 + i0);
            va.x += coef*ka.x; va.y += coef*ka.y; va.z += coef*ka.z; va.w += coef*ka.w;
            vb.x += coef*kb.x; vb.y += coef*kb.y; vb.z += coef*kb.z; vb.w += coef*kb.w;
        }
        unsigned long long* d = sd + p*65 + i0;
        d[0] = pack2(va.x, vb.x); d[1] = pack2(va.y, vb.y);
        d[2] = pack2(va.z, vb.z); d[3] = pack2(va.w, vb.w);
    }
    __syncthreads();

    int c4 = t & 15, rg = t >> 4;             // cols c4*4..+3, pairs rg*2..+1
    unsigned long long acc[2][4];
    #pragma unroll
    for (int p = 0; p < 2; ++p)
        #pragma unroll
        for (int c = 0; c < 4; ++c) acc[p][c] = 0ull;

    const unsigned long long* Rp = sd + rg*2*65;
    const unsigned long long* Wp = Whd + c4*2;

    #pragma unroll 8
    for (int i = 0; i < 64; ++i) {
        ulonglong2 w01 = *(const ulonglong2*)(Wp + (size_t)(i*2)*32);
        ulonglong2 w23 = *(const ulonglong2*)(Wp + (size_t)(i*2 + 1)*32);
        #pragma unroll
        for (int p = 0; p < 2; ++p) {
            unsigned long long r = Rp[p*65 + i];
            fma2(acc[p][0], r, w01.x); fma2(acc[p][1], r, w01.y);
            fma2(acc[p][2], r, w23.x); fma2(acc[p][3], r, w23.y);
        }
    }

    int hd = c4 >> 2, dh0 = (c4 & 3)*4;
    float4 av  = *(const float4*)(As + c4*4);
    float4 dvv = *(const float4*)(Ad + c4*4);

    #pragma unroll
    for (int pp = 0; pp < 2; ++pp) {
        float lo[4], hi[4];
        #pragma unroll
        for (int c = 0; c < 4; ++c) unpack2(lo[c], hi[c], acc[pp][c]);
        #pragma unroll
        for (int rr = 0; rr < 2; ++rr) {
            float* v = rr ? hi : lo;
            int gr = rowbase + rg*4 + pp*2 + rr;
            int bb = gr >> 11, n = gr & 2047;
            *(float4*)(g_h + (((size_t)(bb*HEADS + hd))*NN + n)*DHD + dh0)
                = make_float4(v[0], v[1], v[2], v[3]);
            float ps = v[0]*av.x + v[1]*av.y + v[2]*av.z + v[3]*av.w;
            float pd = v[0]*dvv.x + v[1]*dvv.y + v[2]*dvv.z + v[3]*dvv.w;
            ps += __shfl_xor_sync(0xffffffffu, ps, 1);
            ps += __shfl_xor_sync(0xffffffffu, ps, 2);
            pd += __shfl_xor_sync(0xffffffffu, pd, 1);
            pd += __shfl_xor_sync(0xffffffffu, pd, 2);
            if ((c4 & 3) == 0) {
                int o = (bb*HEADS + hd)*NN + n;
                g_es[o] = ps;
                g_ed[o] = pd;
            }
        }
    }
}

// ---------------- edge softmax + aggregation + RK4 bookkeeping ---------------
// smem words: h 2048*16 | wp 19456 (16B-aligned) | s 2048 | d 1024 | roff 1025
//             | ord 1024 | red 33
#define W_CAP 19456
#define SMEM_EDGE ((2048*16 + W_CAP + 2048 + 1024 + 1025 + 1024 + 35)*4)

// process one quad of packed (w|src) edges
#define EDGE_QUAD(P)                                                        \
    do {                                                                    \
        float w0 = __uint_as_float((P).x);                                  \
        float w1 = __uint_as_float((P).y);                                  \
        float w2 = __uint_as_float((P).z);                                  \
        float w3 = __uint_as_float((P).w);                                  \
        float2 h0 = *(const float2*)(hbase + ((P).x & 0x7FFu)*16);          \
        float2 h1 = *(const float2*)(hbase + ((P).y & 0x7FFu)*16);          \
        float2 h2 = *(const float2*)(hbase + ((P).z & 0x7FFu)*16);          \
        float2 h3 = *(const float2*)(hbase + ((P).w & 0x7FFu)*16);          \
        a0x = fmaf(w0, h0.x, a0x); a0y = fmaf(w0, h0.y, a0y);               \
        a1x = fmaf(w1, h1.x, a1x); a1y = fmaf(w1, h1.y, a1y);               \
        a2x = fmaf(w2, h2.x, a2x); a2y = fmaf(w2, h2.y, a2y);               \
        a3x = fmaf(w3, h3.x, a3x); a3y = fmaf(w3, h3.y, a3y);               \
        ws0 += w0 + w1;                                                     \
        ws1 += w2 + w3;                                                     \
    } while (0)

__global__ void __launch_bounds__(1024) k_edge(const float* __restrict__ bias_g, int mode) {
    extern __shared__ float sm[];
    float* h_sl = sm;                              // 2048*16 (natural layout)
    unsigned int* wp = (unsigned int*)(h_sl + 2048*16);  // 19456, 16B-aligned
    float* s_sl = (float*)(wp + W_CAP);            // 2048
    float* d_sl = s_sl + 2048;                     // 1024
    int*   roff = (int*)(d_sl + 1024);             // 1025
    int*   ord  = roff + 1025;                     // 1024
    float* red  = (float*)(ord + 1024);            // 33

    int t = threadIdx.x;
    int b  = blockIdx.x >> 3;
    int hd = (blockIdx.x >> 1) & 3;
    int halfblk = blockIdx.x & 1;
    int n0 = halfblk*1024;
    int sbase = (b*HEADS + hd)*NN;

    int e0 = g_rowoff[n0];                 // multiple of 4
    int e1 = g_rowoff[n0 + 1024];

    // ---- phase A: stage h (natural), scores, roff, order; block max src score
    const float4* hp = (const float4*)(g_h + (size_t)sbase*DHD);
    #pragma unroll
    for (int it = 0; it < 8; ++it)
        ((float4*)h_sl)[it*1024 + t] = hp[it*1024 + t];
    float lm = -INFINITY;
    #pragma unroll
    for (int it = 0; it < 2; ++it) {
        int i = it*1024 + t;
        float v = g_es[sbase + i];
        s_sl[i] = v;
        lm = fmaxf(lm, v);
    }
    d_sl[t] = g_ed[sbase + n0 + t];
    roff[t] = g_rowoff[n0 + t] - e0;
    ord[t]  = g_order[n0 + t];
    if (t == 0) roff[1024] = e1 - e0;
    #pragma unroll
    for (int o = 16; o > 0; o >>= 1) lm = fmaxf(lm, __shfl_xor_sync(0xffffffffu, lm, o));
    if ((t & 31) == 0) red[t >> 5] = lm;
    __syncthreads();
    if (t == 0) {
        float S = red[0];
        #pragma unroll
        for (int i = 1; i < 32; ++i) S = fmaxf(S, red[i]);
        red[32] = S;
    }
    __syncthreads();
    float S = red[32];

    // ---- phase B: per-edge weight packed (w[31:11] | src[10:0]); pads -> 0
    for (int j = e0 + t; j < e1; j += 1024) {
        unsigned int p = g_csrboth[j];
        unsigned int w_out = 0u;
        if (p != 0xFFFFFFFFu) {
            int s  = (int)(p & 0xFFFFu);
            int dl = (int)(p >> 16) - n0;
            float dv = d_sl[dl];
            float x  = s_sl[s] + dv;
            float lg = (x > 0.f) ? x : 0.2f*x;
            float xm = S + dv;
            float m  = (xm > 0.f) ? xm : 0.2f*xm;
            float w  = __expf(lg - m);
            w_out = (__float_as_uint(w) & 0xFFFFF800u) | (unsigned int)s;
        }
        wp[j - e0] = w_out;
    }
    __syncthreads();

    // ---- phase C: 8 lanes/node, prefetched LDS.128 quads --------------------
    int warp = t >> 5, lane = t & 31;
    int g  = lane >> 3;
    int l8 = lane & 7;
    float2 bias2 = *(const float2*)(bias_g + hd*16 + 2*l8);
    const float* hbase = h_sl + 2*l8;

    for (int k = 0; k < 8; ++k) {
        int idx = k*128 + warp*4 + g;
        int nl  = ord[idx];
        int j   = roff[nl];
        int r1  = roff[nl+1];
        float a0x=0.f,a0y=0.f,a1x=0.f,a1y=0.f;
        float a2x=0.f,a2y=0.f,a3x=0.f,a3y=0.f;
        float ws0=0.f, ws1=0.f;
        if (j < r1) {
            uint4 P = *(const uint4*)(wp + j);
            j += 4;
            for (; j < r1; j += 4) {
                uint4 Pn = *(const uint4*)(wp + j);   // prefetch next quad
                EDGE_QUAD(P);
                P = Pn;
            }
            EDGE_QUAD(P);
        }
        float ax = (a0x + a1x) + (a2x + a3x);
        float ay = (a0y + a1y) + (a2y + a3y);
        float ws = ws0 + ws1;
        float inv = (ws > 0.f) ? 1.0f/ws : 0.f;
        float kvx = ax*inv + bias2.x;
        float kvy = ay*inv + bias2.y;
        int n = n0 + nl;
        size_t o = ((size_t)(b*NN + n))*64 + hd*16 + 2*l8;
        if (mode == 0) {
            *(float2*)(g_k + o)   = make_float2(kvx, kvy);
            *(float2*)(g_acc + o) = make_float2(kvx, kvy);
        } else if (mode == 1) {
            *(float2*)(g_k + o) = make_float2(kvx, kvy);
            float2 ac = *(float2*)(g_acc + o);
            *(float2*)(g_acc + o) = make_float2(ac.x + 2.f*kvx, ac.y + 2.f*kvy);
        } else {
            float2 ac = *(float2*)(g_acc + o);
            float2 yv = *(float2*)(g_y + o);
            *(float2*)(g_y + o) = make_float2(yv.x + DT6F*(ac.x + kvx),
                                              yv.y + DT6F*(ac.y + kvy));
        }
    }
}

// ---------------- output MLP -------------------------------------------------
__global__ void __launch_bounds__(256) k_out(const float* __restrict__ W1, const float* __restrict__ b1,
                                             const float* __restrict__ W2, const float* __restrict__ b2,
                                             float* __restrict__ out) {
    __shared__ float W1s[4096], W2s[4096];
    __shared__ float b1s[64], b2s[64];
    __shared__ float srow[8][136];
    int t = threadIdx.x;
    for (int i = t; i < 1024; i += 256) {
        ((float4*)W1s)[i] = ((const float4*)W1)[i];
        ((float4*)W2s)[i] = ((const float4*)W2)[i];
    }
    if (t < 64) { b1s[t] = b1[t]; b2s[t] = b2[t]; }
    __syncthreads();

    int warp = t >> 5, lane = t & 31, half = lane >> 4, hl = lane & 15;
    float* sr = &srow[warp][half*68];
    int rowbase = blockIdx.x*64 + warp*8;
    int j0 = hl*4;

    for (int it = 0; it < 4; ++it) {
        int gr = rowbase + it*2 + half;
        float4 v = ((const float4*)(g_y + (size_t)gr*64))[hl];
        sr[hl*4+0] = v.x; sr[hl*4+1] = v.y; sr[hl*4+2] = v.z; sr[hl*4+3] = v.w;
        __syncwarp();
        float4 a = make_float4(0.f, 0.f, 0.f, 0.f);
        #pragma unroll 8
        for (int i = 0; i < 64; ++i) {
            float rv = sr[i];
            float4 w4 = ((const float4*)(W1s + i*64))[hl];
            a.x += rv*w4.x; a.y += rv*w4.y; a.z += rv*w4.z; a.w += rv*w4.w;
        }
        a.x = tanhf(a.x + b1s[j0]);
        a.y = tanhf(a.y + b1s[j0+1]);
        a.z = tanhf(a.z + b1s[j0+2]);
        a.w = tanhf(a.w + b1s[j0+3]);
        __syncwarp();
        sr[hl*4+0] = a.x; sr[hl*4+1] = a.y; sr[hl*4+2] = a.z; sr[hl*4+3] = a.w;
        __syncwarp();
        float4 o = make_float4(0.f, 0.f, 0.f, 0.f);
        #pragma unroll 8
        for (int i = 0; i < 64; ++i) {
            float rv = sr[i];
            float4 w4 = ((const float4*)(W2s + i*64))[hl];
            o.x += rv*w4.x; o.y += rv*w4.y; o.z += rv*w4.z; o.w += rv*w4.w;
        }
        o.x += b2s[j0]; o.y += b2s[j0+1]; o.z += b2s[j0+2]; o.w += b2s[j0+3];
        ((float4*)(out + (size_t)gr*64))[hl] = o;
        __syncwarp();
    }
}

// ---------------- launch -----------------------------------------------------
extern "C" void kernel_launch(void* const* d_in, const int* in_sizes, int n_in,
                              void* d_out, int out_size) {
    const float* inputs = (const float*)d_in[0];
    const float* w_in   = (const float*)d_in[1];
    const float* b_in   = (const float*)d_in[2];
    const float* Wh     = (const float*)d_in[3];
    const float* bias_g = (const float*)d_in[4];
    const float* a_src  = (const float*)d_in[5];
    const float* a_dst  = (const float*)d_in[6];
    const float* w1     = (const float*)d_in[7];
    const float* b1     = (const float*)d_in[8];
    const float* w2     = (const float*)d_in[9];
    const float* b2     = (const float*)d_in[10];
    const int*   src    = (const int*)d_in[11];
    const int*   dst    = (const int*)d_in[12];
    float* out = (float*)d_out;

    cudaFuncSetAttribute(k_edge, cudaFuncAttributeMaxDynamicSharedMemorySize, SMEM_EDGE);
    cudaFuncSetAttribute(k_gemm, cudaFuncAttributeMaxDynamicSharedMemorySize, SMEM_GEMM);

    // slot 4 (profiled) = first real k_gemm (v9)
    k_input<<<(BB*NN*HH)/256, 256>>>(inputs, w_in, b_in);   // zeros cnt, sentinels csr
    k_hist<<<EE/256, 256>>>(dst);
    k_scan<<<1, 256>>>();
    k_gemm<<<512, 256, SMEM_GEMM>>>(Wh, a_src, a_dst, 0.f);
    k_fill<<<EE/256, 256>>>(src, dst);

    const float c2 = 0.05f;
    const float c4 = 0.1f;
    for (int s = 0; s < STEPS; ++s) {
        if (s != 0) k_gemm<<<512, 256, SMEM_GEMM>>>(Wh, a_src, a_dst, 0.f);
        k_edge<<<128, 1024, SMEM_EDGE>>>(bias_g, 0);
        k_gemm<<<512, 256, SMEM_GEMM>>>(Wh, a_src, a_dst, c2);
        k_edge<<<128, 1024, SMEM_EDGE>>>(bias_g, 1);
        k_gemm<<<512, 256, SMEM_GEMM>>>(Wh, a_src, a_dst, c2);
        k_edge<<<128, 1024, SMEM_EDGE>>>(bias_g, 1);
        k_gemm<<<512, 256, SMEM_GEMM>>>(Wh, a_src, a_dst, c4);
        k_edge<<<128, 1024, SMEM_EDGE>>>(bias_g, 2);
    }
    k_out<<<512, 256>>>(w1, b1, w2, b2, out);
}

// round 14
// speedup vs baseline: 1.0907x; 1.0907x over previous
#include <cuda_runtime.h>
#include <math.h>

#define BB 16
#define SS 12
#define NN 2048
#define HH 64
#define HEADS 4
#define DHD 16
#define EE 32768
#define EPAD_MAX 40960
#define STEPS 12
#define DT6F ((float)(0.1/6.0))

// ---------------- scratch ----------------------------------------------------
__device__ float g_y[BB*NN*HH];
__device__ float g_h[BB*HEADS*NN*DHD];     // [b][hd][n][16]
__device__ float g_es[BB*HEADS*NN];
__device__ float g_ed[BB*HEADS*NN];
__device__ float g_yeff[BB*NN*HH];         // y + c_next*k (written by k_edge)
__device__ float g_acc[BB*NN*HH];
__device__ int   g_rowoff[NN+1];           // PADDED (multiples of 4) offsets
__device__ int   g_cnt[NN];
__device__ int   g_cursor[NN];
__device__ int   g_order[NN];
__device__ unsigned int g_csrboth[EPAD_MAX]; // (dst<<16)|src ; 0xFFFFFFFF = pad

// ---------------- f32x2 helpers ----------------------------------------------
__device__ __forceinline__ void fma2(unsigned long long &d, unsigned long long a,
                                     unsigned long long b) {
    asm("fma.rn.f32x2 %0, %1, %2, %0;" : "+l"(d) : "l"(a), "l"(b));
}
__device__ __forceinline__ unsigned long long pack2(float lo, float hi) {
    unsigned long long r;
    asm("mov.b64 %0, {%1,%2};" : "=l"(r) : "f"(lo), "f"(hi));
    return r;
}
__device__ __forceinline__ void unpack2(float &lo, float &hi, unsigned long long v) {
    asm("mov.b64 {%0,%1}, %2;" : "=f"(lo), "=f"(hi) : "l"(v));
}

// ---------------- input projection + counter/sentinel init -------------------
__global__ void k_input(const float* __restrict__ inp, const float* __restrict__ w_in,
                        const float* __restrict__ b_in) {
    int idx = blockIdx.x*blockDim.x + threadIdx.x;
    if (idx < NN) g_cnt[idx] = 0;
    if (idx < EPAD_MAX) g_csrboth[idx] = 0xFFFFFFFFu;
    if (idx >= BB*NN*HH) return;
    int h  = idx & 63;
    int bn = idx >> 6;
    int b  = bn >> 11;
    int n  = bn & 2047;
    const float* ip = inp + ((size_t)(b*SS + 0)*NN + n)*2;
    g_y[idx] = ip[0]*w_in[h] + ip[1]*w_in[64+h] + b_in[h];
}

__global__ void k_hist(const int* __restrict__ dst) {
    int e = blockIdx.x*blockDim.x + threadIdx.x;
    if (e < EE) atomicAdd(&g_cnt[dst[e]], 1);
}

// scan (padded degrees) + degree-sort (single block, 256 threads)
__global__ void k_scan() {
    __shared__ int part[256];
    __shared__ int dh[2][64];
    int t = threadIdx.x;
    if (t < 128) { dh[0][t & 63] = 0; dh[1][t & 63] = 0; }
    int base = t*8;
    int loc[8];
    int s = 0;
    #pragma unroll
    for (int i = 0; i < 8; ++i) {
        loc[i] = s;
        s += (g_cnt[base+i] + 3) & ~3;       // pad each segment to mult of 4
    }
    part[t] = s;
    __syncthreads();
    for (int off = 1; off < 256; off <<= 1) {
        int v = (t >= off) ? part[t-off] : 0;
        __syncthreads();
        part[t] += v;
        __syncthreads();
    }
    int excl = (t == 0) ? 0 : part[t-1];
    #pragma unroll
    for (int i = 0; i < 8; ++i) {
        int v = excl + loc[i];
        g_rowoff[base+i] = v;
        g_cursor[base+i] = v;
    }
    if (t == 255) g_rowoff[NN] = part[255];
    #pragma unroll
    for (int i = 0; i < 8; ++i) {
        int n = base + i;
        int d = min(g_cnt[n], 63);
        atomicAdd(&dh[n >> 10][d], 1);
    }
    __syncthreads();
    if (t < 2) {
        int acc = 0;
        for (int d = 0; d < 64; ++d) { int c = dh[t][d]; dh[t][d] = acc; acc += c; }
    }
    __syncthreads();
    #pragma unroll
    for (int i = 0; i < 8; ++i) {
        int n = base + i;
        int half = n >> 10;
        int d = min(g_cnt[n], 63);
        int pos = atomicAdd(&dh[half][d], 1);
        g_order[half*1024 + pos] = n & 1023;
    }
}

__global__ void k_fill(const int* __restrict__ src, const int* __restrict__ dst) {
    int e = blockIdx.x*blockDim.x + threadIdx.x;
    if (e < EE) {
        int d = dst[e];
        int p = atomicAdd(&g_cursor[d], 1);
        g_csrboth[p] = ((unsigned int)d << 16) | (unsigned int)src[e];
    }
}

// ---------------- stage GEMM v6': 128 thr, tile 8 row-pairs x 4 cols ---------
// Single-source staging: reads g_y (stage 1) or g_yeff (stages 2-4).
#define SD_ULL   (64*65)
#define WHD_ULL  (64*2*16*2)
#define SMEM_GEMM ((SD_ULL + WHD_ULL)*8 + 128*4)

__global__ void __launch_bounds__(128, 3) k_gemm(const float* __restrict__ Wh,
                                                 const float* __restrict__ a_src,
                                                 const float* __restrict__ a_dst,
                                                 int use_yeff) {
    extern __shared__ unsigned long long smg[];
    unsigned long long* sd  = smg;                 // 64 pairs x 65
    unsigned long long* Whd = smg + SD_ULL;        // 4096 (k-interleaved dup)
    float* As = (float*)(smg + SD_ULL + WHD_ULL);
    float* Ad = As + 64;

    int t = threadIdx.x;
    int rowbase = blockIdx.x*128;
    const float* ys = use_yeff ? g_yeff : g_y;

    // stage Wh duplicated: Whd[((i*2+q2)*16 + c4)*2 + su], c = c4*4 + q2*2 + su
    #pragma unroll
    for (int it = 0; it < 8; ++it) {
        int idx = it*128 + t;                 // float4 index 0..1023
        int i  = idx >> 4;
        int c0 = (idx & 15)*4;
        float4 w = ((const float4*)Wh)[idx];
        float v[4] = {w.x, w.y, w.z, w.w};
        #pragma unroll
        for (int q = 0; q < 4; ++q) {
            int c = c0 + q;
            int c4i = c >> 2, sub = c & 3;
            Whd[((i*2 + (sub >> 1))*16 + c4i)*2 + (sub & 1)] = pack2(v[q], v[q]);
        }
    }
    if (t < 64) { As[t] = a_src[t]; Ad[t] = a_dst[t]; }

    // stage 128 rows as 64 pairs (ys[2p][i], ys[2p+1][i]), pad 65
    #pragma unroll
    for (int it = 0; it < 8; ++it) {
        int q  = it*128 + t;                  // 0..1023
        int p  = q >> 4;
        int i0 = (q & 15)*4;
        int gr = rowbase + p*2;
        float4 va = *(const float4*)(ys + (size_t)gr*64 + i0);
        float4 vb = *(const float4*)(ys + (size_t)(gr+1)*64 + i0);
        unsigned long long* d = sd + p*65 + i0;
        d[0] = pack2(va.x, vb.x); d[1] = pack2(va.y, vb.y);
        d[2] = pack2(va.z, vb.z); d[3] = pack2(va.w, vb.w);
    }
    __syncthreads();

    int c4 = t & 15, rg = t >> 4;             // cols c4*4..+3, pairs rg*8..+7
    unsigned long long acc[8][4];
    #pragma unroll
    for (int p = 0; p < 8; ++p)
        #pragma unroll
        for (int c = 0; c < 4; ++c) acc[p][c] = 0ull;

    const unsigned long long* Rp = sd + rg*8*65;
    const unsigned long long* Wp = Whd + c4*2;

    #pragma unroll 4
    for (int i = 0; i < 64; ++i) {
        ulonglong2 w01 = *(const ulonglong2*)(Wp + (size_t)(i*2)*32);
        ulonglong2 w23 = *(const ulonglong2*)(Wp + (size_t)(i*2 + 1)*32);
        #pragma unroll
        for (int p = 0; p < 8; ++p) {
            unsigned long long r = Rp[p*65 + i];
            fma2(acc[p][0], r, w01.x); fma2(acc[p][1], r, w01.y);
            fma2(acc[p][2], r, w23.x); fma2(acc[p][3], r, w23.y);
        }
    }

    int hd = c4 >> 2, dh0 = (c4 & 3)*4;
    float4 av  = *(const float4*)(As + c4*4);
    float4 dvv = *(const float4*)(Ad + c4*4);

    #pragma unroll
    for (int pp = 0; pp < 8; ++pp) {
        float lo[4], hi[4];
        #pragma unroll
        for (int c = 0; c < 4; ++c) unpack2(lo[c], hi[c], acc[pp][c]);
        #pragma unroll
        for (int rr = 0; rr < 2; ++rr) {
            float* v = rr ? hi : lo;
            int gr = rowbase + rg*16 + pp*2 + rr;
            int bb = gr >> 11, n = gr & 2047;
            *(float4*)(g_h + (((size_t)(bb*HEADS + hd))*NN + n)*DHD + dh0)
                = make_float4(v[0], v[1], v[2], v[3]);
            float ps = v[0]*av.x + v[1]*av.y + v[2]*av.z + v[3]*av.w;
            float pd = v[0]*dvv.x + v[1]*dvv.y + v[2]*dvv.z + v[3]*dvv.w;
            ps += __shfl_xor_sync(0xffffffffu, ps, 1);
            ps += __shfl_xor_sync(0xffffffffu, ps, 2);
            pd += __shfl_xor_sync(0xffffffffu, pd, 1);
            pd += __shfl_xor_sync(0xffffffffu, pd, 2);
            if ((c4 & 3) == 0) {
                int o = (bb*HEADS + hd)*NN + n;
                g_es[o] = ps;
                g_ed[o] = pd;
            }
        }
    }
}

// ---------------- edge softmax + aggregation + RK4 bookkeeping ---------------
// smem words: h 2048*16 | wp 19456 (16B-aligned) | s 2048 | d 1024 | roff 1025
//             | ord 1024 | red 33
#define W_CAP 19456
#define SMEM_EDGE ((2048*16 + W_CAP + 2048 + 1024 + 1025 + 1024 + 35)*4)

__global__ void __launch_bounds__(1024) k_edge(const float* __restrict__ bias_g,
                                               int mode, float cnext) {
    extern __shared__ float sm[];
    float* h_sl = sm;                              // 2048*16 (natural layout)
    unsigned int* wp = (unsigned int*)(h_sl + 2048*16);  // 19456, 16B-aligned
    float* s_sl = (float*)(wp + W_CAP);            // 2048
    float* d_sl = s_sl + 2048;                     // 1024
    int*   roff = (int*)(d_sl + 1024);             // 1025
    int*   ord  = roff + 1025;                     // 1024
    float* red  = (float*)(ord + 1024);            // 33

    int t = threadIdx.x;
    int b  = blockIdx.x >> 3;
    int hd = (blockIdx.x >> 1) & 3;
    int halfblk = blockIdx.x & 1;
    int n0 = halfblk*1024;
    int sbase = (b*HEADS + hd)*NN;

    int e0 = g_rowoff[n0];                 // multiple of 4
    int e1 = g_rowoff[n0 + 1024];

    // ---- phase A: stage h (natural), scores, roff, order; block max src score
    const float4* hp = (const float4*)(g_h + (size_t)sbase*DHD);
    #pragma unroll
    for (int it = 0; it < 8; ++it)
        ((float4*)h_sl)[it*1024 + t] = hp[it*1024 + t];
    float lm = -INFINITY;
    #pragma unroll
    for (int it = 0; it < 2; ++it) {
        int i = it*1024 + t;
        float v = g_es[sbase + i];
        s_sl[i] = v;
        lm = fmaxf(lm, v);
    }
    d_sl[t] = g_ed[sbase + n0 + t];
    roff[t] = g_rowoff[n0 + t] - e0;
    ord[t]  = g_order[n0 + t];
    if (t == 0) roff[1024] = e1 - e0;
    #pragma unroll
    for (int o = 16; o > 0; o >>= 1) lm = fmaxf(lm, __shfl_xor_sync(0xffffffffu, lm, o));
    if ((t & 31) == 0) red[t >> 5] = lm;
    __syncthreads();
    if (t == 0) {
        float S = red[0];
        #pragma unroll
        for (int i = 1; i < 32; ++i) S = fmaxf(S, red[i]);
        red[32] = S;
    }
    __syncthreads();
    float S = red[32];

    // ---- phase B: per-edge weight packed (w[31:11] | src[10:0]); pads -> 0
    for (int j = e0 + t; j < e1; j += 1024) {
        unsigned int p = g_csrboth[j];
        unsigned int w_out = 0u;
        if (p != 0xFFFFFFFFu) {
            int s  = (int)(p & 0xFFFFu);
            int dl = (int)(p >> 16) - n0;
            float dv = d_sl[dl];
            float x  = s_sl[s] + dv;
            float lg = (x > 0.f) ? x : 0.2f*x;
            float xm = S + dv;
            float m  = (xm > 0.f) ? xm : 0.2f*xm;
            float w  = __expf(lg - m);
            w_out = (__float_as_uint(w) & 0xFFFFF800u) | (unsigned int)s;
        }
        wp[j - e0] = w_out;
    }
    __syncthreads();

    // ---- phase C: 8 lanes/node, LDS.128 quads, no weight mask ---------------
    int warp = t >> 5, lane = t & 31;
    int g  = lane >> 3;
    int l8 = lane & 7;
    float2 bias2 = *(const float2*)(bias_g + hd*16 + 2*l8);
    const float* hbase = h_sl + 2*l8;

    for (int k = 0; k < 8; ++k) {
        int idx = k*128 + warp*4 + g;
        int nl  = ord[idx];
        int j   = roff[nl];
        int r1  = roff[nl+1];
        float a0x=0.f,a0y=0.f,a1x=0.f,a1y=0.f;
        float a2x=0.f,a2y=0.f,a3x=0.f,a3y=0.f;
        float ws0=0.f, ws1=0.f;
        for (; j < r1; j += 4) {
            uint4 P = *(const uint4*)(wp + j);
            float w0 = __uint_as_float(P.x);
            float w1 = __uint_as_float(P.y);
            float w2 = __uint_as_float(P.z);
            float w3 = __uint_as_float(P.w);
            float2 h0 = *(const float2*)(hbase + (P.x & 0x7FFu)*16);
            float2 h1 = *(const float2*)(hbase + (P.y & 0x7FFu)*16);
            float2 h2 = *(const float2*)(hbase + (P.z & 0x7FFu)*16);
            float2 h3 = *(const float2*)(hbase + (P.w & 0x7FFu)*16);
            a0x = fmaf(w0, h0.x, a0x); a0y = fmaf(w0, h0.y, a0y);
            a1x = fmaf(w1, h1.x, a1x); a1y = fmaf(w1, h1.y, a1y);
            a2x = fmaf(w2, h2.x, a2x); a2y = fmaf(w2, h2.y, a2y);
            a3x = fmaf(w3, h3.x, a3x); a3y = fmaf(w3, h3.y, a3y);
            ws0 += w0 + w1;
            ws1 += w2 + w3;
        }
        float ax = (a0x + a1x) + (a2x + a3x);
        float ay = (a0y + a1y) + (a2y + a3y);
        float ws = ws0 + ws1;
        float inv = (ws > 0.f) ? 1.0f/ws : 0.f;
        float kvx = ax*inv + bias2.x;
        float kvy = ay*inv + bias2.y;
        int n = n0 + nl;
        size_t o = ((size_t)(b*NN + n))*64 + hd*16 + 2*l8;
        float2 yv = *(float2*)(g_y + o);
        if (mode == 0) {
            g_acc[o]   = kvx;        g_acc[o+1]   = kvy;
            g_yeff[o]  = yv.x + cnext*kvx;
            g_yeff[o+1] = yv.y + cnext*kvy;
        } else if (mode == 1) {
            float2 ac = *(float2*)(g_acc + o);
            g_acc[o]   = ac.x + 2.f*kvx;
            g_acc[o+1] = ac.y + 2.f*kvy;
            g_yeff[o]  = yv.x + cnext*kvx;
            g_yeff[o+1] = yv.y + cnext*kvy;
        } else {
            float2 ac = *(float2*)(g_acc + o);
            *(float2*)(g_y + o) = make_float2(yv.x + DT6F*(ac.x + kvx),
                                              yv.y + DT6F*(ac.y + kvy));
        }
    }
}

// ---------------- output MLP -------------------------------------------------
__global__ void __launch_bounds__(256) k_out(const float* __restrict__ W1, const float* __restrict__ b1,
                                             const float* __restrict__ W2, const float* __restrict__ b2,
                                             float* __restrict__ out) {
    __shared__ float W1s[4096], W2s[4096];
    __shared__ float b1s[64], b2s[64];
    __shared__ float srow[8][136];
    int t = threadIdx.x;
    for (int i = t; i < 1024; i += 256) {
        ((float4*)W1s)[i] = ((const float4*)W1)[i];
        ((float4*)W2s)[i] = ((const float4*)W2)[i];
    }
    if (t < 64) { b1s[t] = b1[t]; b2s[t] = b2[t]; }
    __syncthreads();

    int warp = t >> 5, lane = t & 31, half = lane >> 4, hl = lane & 15;
    float* sr = &srow[warp][half*68];
    int rowbase = blockIdx.x*64 + warp*8;
    int j0 = hl*4;

    for (int it = 0; it < 4; ++it) {
        int gr = rowbase + it*2 + half;
        float4 v = ((const float4*)(g_y + (size_t)gr*64))[hl];
        sr[hl*4+0] = v.x; sr[hl*4+1] = v.y; sr[hl*4+2] = v.z; sr[hl*4+3] = v.w;
        __syncwarp();
        float4 a = make_float4(0.f, 0.f, 0.f, 0.f);
        #pragma unroll 8
        for (int i = 0; i < 64; ++i) {
            float rv = sr[i];
            float4 w4 = ((const float4*)(W1s + i*64))[hl];
            a.x += rv*w4.x; a.y += rv*w4.y; a.z += rv*w4.z; a.w += rv*w4.w;
        }
        a.x = tanhf(a.x + b1s[j0]);
        a.y = tanhf(a.y + b1s[j0+1]);
        a.z = tanhf(a.z + b1s[j0+2]);
        a.w = tanhf(a.w + b1s[j0+3]);
        __syncwarp();
        sr[hl*4+0] = a.x; sr[hl*4+1] = a.y; sr[hl*4+2] = a.z; sr[hl*4+3] = a.w;
        __syncwarp();
        float4 o = make_float4(0.f, 0.f, 0.f, 0.f);
        #pragma unroll 8
        for (int i = 0; i < 64; ++i) {
            float rv = sr[i];
            float4 w4 = ((const float4*)(W2s + i*64))[hl];
            o.x += rv*w4.x; o.y += rv*w4.y; o.z += rv*w4.z; o.w += rv*w4.w;
        }
        o.x += b2s[j0]; o.y += b2s[j0+1]; o.z += b2s[j0+2]; o.w += b2s[j0+3];
        ((float4*)(out + (size_t)gr*64))[hl] = o;
        __syncwarp();
    }
}

// ---------------- launch -----------------------------------------------------
extern "C" void kernel_launch(void* const* d_in, const int* in_sizes, int n_in,
                              void* d_out, int out_size) {
    const float* inputs = (const float*)d_in[0];
    const float* w_in   = (const float*)d_in[1];
    const float* b_in   = (const float*)d_in[2];
    const float* Wh     = (const float*)d_in[3];
    const float* bias_g = (const float*)d_in[4];
    const float* a_src  = (const float*)d_in[5];
    const float* a_dst  = (const float*)d_in[6];
    const float* w1     = (const float*)d_in[7];
    const float* b1     = (const float*)d_in[8];
    const float* w2     = (const float*)d_in[9];
    const float* b2     = (const float*)d_in[10];
    const int*   src    = (const int*)d_in[11];
    const int*   dst    = (const int*)d_in[12];
    float* out = (float*)d_out;

    cudaFuncSetAttribute(k_edge, cudaFuncAttributeMaxDynamicSharedMemorySize, SMEM_EDGE);
    cudaFuncSetAttribute(k_gemm, cudaFuncAttributeMaxDynamicSharedMemorySize, SMEM_GEMM);

    // slot 4 (profiled) = first real k_gemm (stage-1: reads g_y, unchanged path)
    k_input<<<(BB*NN*HH)/256, 256>>>(inputs, w_in, b_in);   // zeros cnt, sentinels csr
    k_hist<<<EE/256, 256>>>(dst);
    k_scan<<<1, 256>>>();
    k_gemm<<<256, 128, SMEM_GEMM>>>(Wh, a_src, a_dst, 0);
    k_fill<<<EE/256, 256>>>(src, dst);

    for (int s = 0; s < STEPS; ++s) {
        if (s != 0) k_gemm<<<256, 128, SMEM_GEMM>>>(Wh, a_src, a_dst, 0);
        k_edge<<<128, 1024, SMEM_EDGE>>>(bias_g, 0, 0.05f);
        k_gemm<<<256, 128, SMEM_GEMM>>>(Wh, a_src, a_dst, 1);
        k_edge<<<128, 1024, SMEM_EDGE>>>(bias_g, 1, 0.05f);
        k_gemm<<<256, 128, SMEM_GEMM>>>(Wh, a_src, a_dst, 1);
        k_edge<<<128, 1024, SMEM_EDGE>>>(bias_g, 1, 0.10f);
        k_gemm<<<256, 128, SMEM_GEMM>>>(Wh, a_src, a_dst, 1);
        k_edge<<<128, 1024, SMEM_EDGE>>>(bias_g, 2, 0.f);
    }
    k_out<<<512, 256>>>(w1, b1, w2, b2, out);
}

// round 16
// speedup vs baseline: 1.2004x; 1.1006x over previous
#include <cuda_runtime.h>
#include <cuda_fp16.h>
#include <math.h>

#define BB 16
#define SS 12
#define NN 2048
#define HH 64
#define HEADS 4
#define DHD 16
#define EE 32768
#define EPAD_MAX 40960
#define STEPS 12
#define DT6F ((float)(0.1/6.0))

// ---------------- scratch ----------------------------------------------------
__device__ float g_y[BB*NN*HH];
__device__ unsigned int g_hh[BB*HEADS*NN*8];  // h as packed half2: [b][hd][n][8]
__device__ float g_es[BB*HEADS*NN];
__device__ float g_ed[BB*HEADS*NN];
__device__ float g_k[BB*NN*HH];
__device__ float g_acc[BB*NN*HH];
__device__ int   g_rowoff[NN+1];           // PADDED (multiples of 4) offsets
__device__ int   g_cnt[NN];
__device__ int   g_cursor[NN];
__device__ int   g_order[NN];
__device__ unsigned int g_csrboth[EPAD_MAX]; // (dst<<16)|src ; 0xFFFFFFFF = pad

// ---------------- f32x2 helpers ----------------------------------------------
__device__ __forceinline__ void fma2(unsigned long long &d, unsigned long long a,
                                     unsigned long long b) {
    asm("fma.rn.f32x2 %0, %1, %2, %0;" : "+l"(d) : "l"(a), "l"(b));
}
__device__ __forceinline__ unsigned long long pack2(float lo, float hi) {
    unsigned long long r;
    asm("mov.b64 %0, {%1,%2};" : "=l"(r) : "f"(lo), "f"(hi));
    return r;
}
__device__ __forceinline__ void unpack2(float &lo, float &hi, unsigned long long v) {
    asm("mov.b64 {%0,%1}, %2;" : "=f"(lo), "=f"(hi) : "l"(v));
}

// ---------------- input projection + counter/sentinel init -------------------
__global__ void k_input(const float* __restrict__ inp, const float* __restrict__ w_in,
                        const float* __restrict__ b_in) {
    int idx = blockIdx.x*blockDim.x + threadIdx.x;
    if (idx < NN) g_cnt[idx] = 0;
    if (idx < EPAD_MAX) g_csrboth[idx] = 0xFFFFFFFFu;
    if (idx >= BB*NN*HH) return;
    int h  = idx & 63;
    int bn = idx >> 6;
    int b  = bn >> 11;
    int n  = bn & 2047;
    const float* ip = inp + ((size_t)(b*SS + 0)*NN + n)*2;
    g_y[idx] = ip[0]*w_in[h] + ip[1]*w_in[64+h] + b_in[h];
}

__global__ void k_hist(const int* __restrict__ dst) {
    int e = blockIdx.x*blockDim.x + threadIdx.x;
    if (e < EE) atomicAdd(&g_cnt[dst[e]], 1);
}

// scan (padded degrees) + degree-sort (single block, 256 threads)
__global__ void k_scan() {
    __shared__ int part[256];
    __shared__ int dh[2][64];
    int t = threadIdx.x;
    if (t < 128) { dh[0][t & 63] = 0; dh[1][t & 63] = 0; }
    int base = t*8;
    int loc[8];
    int s = 0;
    #pragma unroll
    for (int i = 0; i < 8; ++i) {
        loc[i] = s;
        s += (g_cnt[base+i] + 3) & ~3;       // pad each segment to mult of 4
    }
    part[t] = s;
    __syncthreads();
    for (int off = 1; off < 256; off <<= 1) {
        int v = (t >= off) ? part[t-off] : 0;
        __syncthreads();
        part[t] += v;
        __syncthreads();
    }
    int excl = (t == 0) ? 0 : part[t-1];
    #pragma unroll
    for (int i = 0; i < 8; ++i) {
        int v = excl + loc[i];
        g_rowoff[base+i] = v;
        g_cursor[base+i] = v;
    }
    if (t == 255) g_rowoff[NN] = part[255];
    #pragma unroll
    for (int i = 0; i < 8; ++i) {
        int n = base + i;
        int d = min(g_cnt[n], 63);
        atomicAdd(&dh[n >> 10][d], 1);
    }
    __syncthreads();
    if (t < 2) {
        int acc = 0;
        for (int d = 0; d < 64; ++d) { int c = dh[t][d]; dh[t][d] = acc; acc += c; }
    }
    __syncthreads();
    #pragma unroll
    for (int i = 0; i < 8; ++i) {
        int n = base + i;
        int half = n >> 10;
        int d = min(g_cnt[n], 63);
        int pos = atomicAdd(&dh[half][d], 1);
        g_order[half*1024 + pos] = n & 1023;
    }
}

__global__ void k_fill(const int* __restrict__ src, const int* __restrict__ dst) {
    int e = blockIdx.x*blockDim.x + threadIdx.x;
    if (e < EE) {
        int d = dst[e];
        int p = atomicAdd(&g_cursor[d], 1);
        g_csrboth[p] = ((unsigned int)d << 16) | (unsigned int)src[e];
    }
}

// ---------------- stage GEMM v6 (R10 best): 128 thr, 8 row-pairs x 4 cols ----
#define SD_ULL   (64*65)
#define WHD_ULL  (64*2*16*2)
#define SMEM_GEMM ((SD_ULL + WHD_ULL)*8 + 128*4)

__global__ void __launch_bounds__(128, 3) k_gemm(const float* __restrict__ Wh,
                                                 const float* __restrict__ a_src,
                                                 const float* __restrict__ a_dst,
                                                 float coef) {
    extern __shared__ unsigned long long smg[];
    unsigned long long* sd  = smg;                 // 64 pairs x 65
    unsigned long long* Whd = smg + SD_ULL;        // 4096 (k-interleaved dup)
    float* As = (float*)(smg + SD_ULL + WHD_ULL);
    float* Ad = As + 64;

    int t = threadIdx.x;
    int rowbase = blockIdx.x*128;

    #pragma unroll
    for (int it = 0; it < 8; ++it) {
        int idx = it*128 + t;                 // float4 index 0..1023
        int i  = idx >> 4;
        int c0 = (idx & 15)*4;
        float4 w = ((const float4*)Wh)[idx];
        float v[4] = {w.x, w.y, w.z, w.w};
        #pragma unroll
        for (int q = 0; q < 4; ++q) {
            int c = c0 + q;
            int c4i = c >> 2, sub = c & 3;
            Whd[((i*2 + (sub >> 1))*16 + c4i)*2 + (sub & 1)] = pack2(v[q], v[q]);
        }
    }
    if (t < 64) { As[t] = a_src[t]; Ad[t] = a_dst[t]; }

    #pragma unroll
    for (int it = 0; it < 8; ++it) {
        int q  = it*128 + t;                  // 0..1023
        int p  = q >> 4;
        int i0 = (q & 15)*4;
        int gr = rowbase + p*2;
        float4 va = *(const float4*)(g_y + (size_t)gr*64 + i0);
        float4 vb = *(const float4*)(g_y + (size_t)(gr+1)*64 + i0);
        if (coef != 0.f) {
            float4 ka = *(const float4*)(g_k + (size_t)gr*64 + i0);
            float4 kb = *(const float4*)(g_k + (size_t)(gr+1)*64 + i0);
            va.x += coef*ka.x; va.y += coef*ka.y; va.z += coef*ka.z; va.w += coef*ka.w;
            vb.x += coef*kb.x; vb.y += coef*kb.y; vb.z += coef*kb.z; vb.w += coef*kb.w;
        }
        unsigned long long* d = sd + p*65 + i0;
        d[0] = pack2(va.x, vb.x); d[1] = pack2(va.y, vb.y);
        d[2] = pack2(va.z, vb.z); d[3] = pack2(va.w, vb.w);
    }
    __syncthreads();

    int c4 = t & 15, rg = t >> 4;             // cols c4*4..+3, pairs rg*8..+7
    unsigned long long acc[8][4];
    #pragma unroll
    for (int p = 0; p < 8; ++p)
        #pragma unroll
        for (int c = 0; c < 4; ++c) acc[p][c] = 0ull;

    const unsigned long long* Rp = sd + rg*8*65;
    const unsigned long long* Wp = Whd + c4*2;

    #pragma unroll 4
    for (int i = 0; i < 64; ++i) {
        ulonglong2 w01 = *(const ulonglong2*)(Wp + (size_t)(i*2)*32);
        ulonglong2 w23 = *(const ulonglong2*)(Wp + (size_t)(i*2 + 1)*32);
        #pragma unroll
        for (int p = 0; p < 8; ++p) {
            unsigned long long r = Rp[p*65 + i];
            fma2(acc[p][0], r, w01.x); fma2(acc[p][1], r, w01.y);
            fma2(acc[p][2], r, w23.x); fma2(acc[p][3], r, w23.y);
        }
    }

    int hd = c4 >> 2, dh0 = (c4 & 3)*4;
    float4 av  = *(const float4*)(As + c4*4);
    float4 dvv = *(const float4*)(Ad + c4*4);

    #pragma unroll
    for (int pp = 0; pp < 8; ++pp) {
        float lo[4], hi[4];
        #pragma unroll
        for (int c = 0; c < 4; ++c) unpack2(lo[c], hi[c], acc[pp][c]);
        #pragma unroll
        for (int rr = 0; rr < 2; ++rr) {
            float* v = rr ? hi : lo;
            int gr = rowbase + rg*16 + pp*2 + rr;
            int bb = gr >> 11, n = gr & 2047;
            // store h as packed half2 (scores below stay fp32)
            __half2 p01 = __floats2half2_rn(v[0], v[1]);
            __half2 p23 = __floats2half2_rn(v[2], v[3]);
            uint2 st;
            st.x = *(unsigned int*)&p01;
            st.y = *(unsigned int*)&p23;
            *(uint2*)(g_hh + (((size_t)(bb*HEADS + hd))*NN + n)*8 + (dh0 >> 1)) = st;
            float ps = v[0]*av.x + v[1]*av.y + v[2]*av.z + v[3]*av.w;
            float pd = v[0]*dvv.x + v[1]*dvv.y + v[2]*dvv.z + v[3]*dvv.w;
            ps += __shfl_xor_sync(0xffffffffu, ps, 1);
            ps += __shfl_xor_sync(0xffffffffu, ps, 2);
            pd += __shfl_xor_sync(0xffffffffu, pd, 1);
            pd += __shfl_xor_sync(0xffffffffu, pd, 2);
            if ((c4 & 3) == 0) {
                int o = (bb*HEADS + hd)*NN + n;
                g_es[o] = ps;
                g_ed[o] = pd;
            }
        }
    }
}

// ---------------- edge softmax + aggregation + RK4 bookkeeping ---------------
// smem words: h2 2048*9 (half2, stride-9 conflict spread) | wp 19456 | s 2048
//             | d 1024 | roff 1025 | ord 1024 | red 33  = 43042 w = 172KB
#define H2_WORDS (2048*9)
#define W_CAP 19456
#define SMEM_EDGE ((H2_WORDS + W_CAP + 2048 + 1024 + 1025 + 1024 + 33)*4)

__global__ void __launch_bounds__(1024) k_edge(const float* __restrict__ bias_g, int mode) {
    extern __shared__ float sm[];
    unsigned int* h2u = (unsigned int*)sm;         // 2048 nodes x 9 half2-words
    unsigned int* wp  = h2u + H2_WORDS;            // 19456, 16B-aligned
    float* s_sl = (float*)(wp + W_CAP);            // 2048
    float* d_sl = s_sl + 2048;                     // 1024
    int*   roff = (int*)(d_sl + 1024);             // 1025
    int*   ord  = roff + 1025;                     // 1024
    float* red  = (float*)(ord + 1024);            // 33

    int t = threadIdx.x;
    int b  = blockIdx.x >> 3;
    int hd = (blockIdx.x >> 1) & 3;
    int halfblk = blockIdx.x & 1;
    int n0 = halfblk*1024;
    int sbase = (b*HEADS + hd)*NN;

    int e0 = g_rowoff[n0];                 // multiple of 4
    int e1 = g_rowoff[n0 + 1024];

    // ---- phase A: stage h (half2, node stride 9), scores, roff, order -------
    const uint4* hp = (const uint4*)(g_hh + (size_t)sbase*8);
    #pragma unroll
    for (int it = 0; it < 4; ++it) {
        int i = it*1024 + t;                  // uint4 index 0..4095
        uint4 v = hp[i];
        int p0 = i*4;                         // half2-word index
        unsigned int* d = h2u + (p0 >> 3)*9 + (p0 & 7);
        d[0] = v.x; d[1] = v.y; d[2] = v.z; d[3] = v.w;
    }
    float lm = -INFINITY;
    #pragma unroll
    for (int it = 0; it < 2; ++it) {
        int i = it*1024 + t;
        float v = g_es[sbase + i];
        s_sl[i] = v;
        lm = fmaxf(lm, v);
    }
    d_sl[t] = g_ed[sbase + n0 + t];
    roff[t] = g_rowoff[n0 + t] - e0;
    ord[t]  = g_order[n0 + t];
    if (t == 0) roff[1024] = e1 - e0;
    #pragma unroll
    for (int o = 16; o > 0; o >>= 1) lm = fmaxf(lm, __shfl_xor_sync(0xffffffffu, lm, o));
    if ((t & 31) == 0) red[t >> 5] = lm;
    __syncthreads();
    if (t == 0) {
        float S = red[0];
        #pragma unroll
        for (int i = 1; i < 32; ++i) S = fmaxf(S, red[i]);
        red[32] = S;
    }
    __syncthreads();
    float S = red[32];

    // ---- phase B: per-edge weight packed (w[31:11] | src[10:0]); pads -> 0
    for (int j = e0 + t; j < e1; j += 1024) {
        unsigned int p = g_csrboth[j];
        unsigned int w_out = 0u;
        if (p != 0xFFFFFFFFu) {
            int s  = (int)(p & 0xFFFFu);
            int dl = (int)(p >> 16) - n0;
            float dv = d_sl[dl];
            float x  = s_sl[s] + dv;
            float lg = (x > 0.f) ? x : 0.2f*x;
            float xm = S + dv;
            float m  = (xm > 0.f) ? xm : 0.2f*xm;
            float w  = __expf(lg - m);
            w_out = (__float_as_uint(w) & 0xFFFFF800u) | (unsigned int)s;
        }
        wp[j - e0] = w_out;
    }
    __syncthreads();

    // ---- phase C: 8 lanes/node, LDS.128 wp quads, half2 h loads -------------
    int warp = t >> 5, lane = t & 31;
    int g  = lane >> 3;
    int l8 = lane & 7;
    float2 bias2 = *(const float2*)(bias_g + hd*16 + 2*l8);
    const __half2* hb2 = ((const __half2*)h2u) + l8;

    for (int k = 0; k < 8; ++k) {
        int idx = k*128 + warp*4 + g;
        int nl  = ord[idx];
        int j   = roff[nl];
        int r1  = roff[nl+1];
        float a0x=0.f,a0y=0.f,a1x=0.f,a1y=0.f;
        float a2x=0.f,a2y=0.f,a3x=0.f,a3y=0.f;
        float ws0=0.f, ws1=0.f;
        for (; j < r1; j += 4) {
            uint4 P = *(const uint4*)(wp + j);
            float w0 = __uint_as_float(P.x);
            float w1 = __uint_as_float(P.y);
            float w2 = __uint_as_float(P.z);
            float w3 = __uint_as_float(P.w);
            float2 h0 = __half22float2(hb2[(P.x & 0x7FFu)*9]);
            float2 h1 = __half22float2(hb2[(P.y & 0x7FFu)*9]);
            float2 h2 = __half22float2(hb2[(P.z & 0x7FFu)*9]);
            float2 h3 = __half22float2(hb2[(P.w & 0x7FFu)*9]);
            a0x = fmaf(w0, h0.x, a0x); a0y = fmaf(w0, h0.y, a0y);
            a1x = fmaf(w1, h1.x, a1x); a1y = fmaf(w1, h1.y, a1y);
            a2x = fmaf(w2, h2.x, a2x); a2y = fmaf(w2, h2.y, a2y);
            a3x = fmaf(w3, h3.x, a3x); a3y = fmaf(w3, h3.y, a3y);
            ws0 += w0 + w1;
            ws1 += w2 + w3;
        }
        float ax = (a0x + a1x) + (a2x + a3x);
        float ay = (a0y + a1y) + (a2y + a3y);
        float ws = ws0 + ws1;
        float inv = (ws > 0.f) ? 1.0f/ws : 0.f;
        float kvx = ax*inv + bias2.x;
        float kvy = ay*inv + bias2.y;
        int n = n0 + nl;
        size_t o = ((size_t)(b*NN + n))*64 + hd*16 + 2*l8;
        if (mode == 0) {
            *(float2*)(g_k + o)   = make_float2(kvx, kvy);
            *(float2*)(g_acc + o) = make_float2(kvx, kvy);
        } else if (mode == 1) {
            *(float2*)(g_k + o) = make_float2(kvx, kvy);
            float2 ac = *(float2*)(g_acc + o);
            *(float2*)(g_acc + o) = make_float2(ac.x + 2.f*kvx, ac.y + 2.f*kvy);
        } else {
            float2 ac = *(float2*)(g_acc + o);
            float2 yv = *(float2*)(g_y + o);
            *(float2*)(g_y + o) = make_float2(yv.x + DT6F*(ac.x + kvx),
                                              yv.y + DT6F*(ac.y + kvy));
        }
    }
}

// ---------------- output MLP -------------------------------------------------
__global__ void __launch_bounds__(256) k_out(const float* __restrict__ W1, const float* __restrict__ b1,
                                             const float* __restrict__ W2, const float* __restrict__ b2,
                                             float* __restrict__ out) {
    __shared__ float W1s[4096], W2s[4096];
    __shared__ float b1s[64], b2s[64];
    __shared__ float srow[8][136];
    int t = threadIdx.x;
    for (int i = t; i < 1024; i += 256) {
        ((float4*)W1s)[i] = ((const float4*)W1)[i];
        ((float4*)W2s)[i] = ((const float4*)W2)[i];
    }
    if (t < 64) { b1s[t] = b1[t]; b2s[t] = b2[t]; }
    __syncthreads();

    int warp = t >> 5, lane = t & 31, half = lane >> 4, hl = lane & 15;
    float* sr = &srow[warp][half*68];
    int rowbase = blockIdx.x*64 + warp*8;
    int j0 = hl*4;

    for (int it = 0; it < 4; ++it) {
        int gr = rowbase + it*2 + half;
        float4 v = ((const float4*)(g_y + (size_t)gr*64))[hl];
        sr[hl*4+0] = v.x; sr[hl*4+1] = v.y; sr[hl*4+2] = v.z; sr[hl*4+3] = v.w;
        __syncwarp();
        float4 a = make_float4(0.f, 0.f, 0.f, 0.f);
        #pragma unroll 8
        for (int i = 0; i < 64; ++i) {
            float rv = sr[i];
            float4 w4 = ((const float4*)(W1s + i*64))[hl];
            a.x += rv*w4.x; a.y += rv*w4.y; a.z += rv*w4.z; a.w += rv*w4.w;
        }
        a.x = tanhf(a.x + b1s[j0]);
        a.y = tanhf(a.y + b1s[j0+1]);
        a.z = tanhf(a.z + b1s[j0+2]);
        a.w = tanhf(a.w + b1s[j0+3]);
        __syncwarp();
        sr[hl*4+0] = a.x; sr[hl*4+1] = a.y; sr[hl*4+2] = a.z; sr[hl*4+3] = a.w;
        __syncwarp();
        float4 o = make_float4(0.f, 0.f, 0.f, 0.f);
        #pragma unroll 8
        for (int i = 0; i < 64; ++i) {
            float rv = sr[i];
            float4 w4 = ((const float4*)(W2s + i*64))[hl];
            o.x += rv*w4.x; o.y += rv*w4.y; o.z += rv*w4.z; o.w += rv*w4.w;
        }
        o.x += b2s[j0]; o.y += b2s[j0+1]; o.z += b2s[j0+2]; o.w += b2s[j0+3];
        ((float4*)(out + (size_t)gr*64))[hl] = o;
        __syncwarp();
    }
}

// ---------------- launch -----------------------------------------------------
extern "C" void kernel_launch(void* const* d_in, const int* in_sizes, int n_in,
                              void* d_out, int out_size) {
    const float* inputs = (const float*)d_in[0];
    const float* w_in   = (const float*)d_in[1];
    const float* b_in   = (const float*)d_in[2];
    const float* Wh     = (const float*)d_in[3];
    const float* bias_g = (const float*)d_in[4];
    const float* a_src  = (const float*)d_in[5];
    const float* a_dst  = (const float*)d_in[6];
    const float* w1     = (const float*)d_in[7];
    const float* b1     = (const float*)d_in[8];
    const float* w2     = (const float*)d_in[9];
    const float* b2     = (const float*)d_in[10];
    const int*   src    = (const int*)d_in[11];
    const int*   dst    = (const int*)d_in[12];
    float* out = (float*)d_out;

    cudaFuncSetAttribute(k_edge, cudaFuncAttributeMaxDynamicSharedMemorySize, SMEM_EDGE);
    cudaFuncSetAttribute(k_gemm, cudaFuncAttributeMaxDynamicSharedMemorySize, SMEM_GEMM);

    // slot 4 (profiled) = first real k_gemm
    k_input<<<(BB*NN*HH)/256, 256>>>(inputs, w_in, b_in);   // zeros cnt, sentinels csr
    k_hist<<<EE/256, 256>>>(dst);
    k_scan<<<1, 256>>>();
    k_gemm<<<256, 128, SMEM_GEMM>>>(Wh, a_src, a_dst, 0.f);
    k_fill<<<EE/256, 256>>>(src, dst);

    const float c2 = 0.05f;
    const float c4 = 0.1f;
    for (int s = 0; s < STEPS; ++s) {
        if (s != 0) k_gemm<<<256, 128, SMEM_GEMM>>>(Wh, a_src, a_dst, 0.f);
        k_edge<<<128, 1024, SMEM_EDGE>>>(bias_g, 0);
        k_gemm<<<256, 128, SMEM_GEMM>>>(Wh, a_src, a_dst, c2);
        k_edge<<<128, 1024, SMEM_EDGE>>>(bias_g, 1);
        k_gemm<<<256, 128, SMEM_GEMM>>>(Wh, a_src, a_dst, c2);
        k_edge<<<128, 1024, SMEM_EDGE>>>(bias_g, 1);
        k_gemm<<<256, 128, SMEM_GEMM>>>(Wh, a_src, a_dst, c4);
        k_edge<<<128, 1024, SMEM_EDGE>>>(bias_g, 2);
    }
    k_out<<<512, 256>>>(w1, b1, w2, b2, out);
}